// round 17
// baseline (speedup 1.0000x reference)
#include <cuda_runtime.h>
#include <cstdint>

#define NB   32
#define NH   64
#define NW   64
#define HO   62
#define WO   62
#define NPB  (HO*WO)            // 3844
#define NSTREAM 296             // 148 CTAs x 2 groups

// A: [cblk 4][kh 3][kw 3][ocb 8][perm 128] fp16x2 (lane-major permuted layout)
__device__ __align__(16) uint32_t g_a16[36*1024];            // 147.5 KB

// ---- SMEM geometry (words) ----
#define BROWW  72               // B words per c2 row (68 data + 4 pad)
#define BBUFW  2304             // one B buffer: [row 4][c2 8][72]
#define AWORDS 36864            // all 36 A tiles
#define SMEMW  (AWORDS + 4*BBUFW)   // + [grp 2][buf 2]
#define SMEMB  (SMEMW*4)        // 184320 B

// ---------------- PTX helpers ----------------
__device__ __forceinline__ uint32_t cvta_s(const void* p) {
    uint32_t a;
    asm("{ .reg .u64 t; cvta.to.shared.u64 t, %1; cvt.u32.u64 %0, t; }" : "=r"(a) : "l"(p));
    return a;
}
__device__ __forceinline__ uint32_t pack_h2(float even, float odd) {
    uint32_t d;
    asm("cvt.rn.f16x2.f32 %0, %1, %2;" : "=r"(d) : "f"(odd), "f"(even));  // lo=even, hi=odd
    return d;
}
__device__ __forceinline__ uint32_t lds32(uint32_t addr) {
    uint32_t v;
    asm volatile("ld.shared.b32 %0,[%1];" : "=r"(v) : "r"(addr));
    return v;
}
__device__ __forceinline__ uint4 lds128(uint32_t addr) {
    uint4 v;
    asm volatile("ld.shared.v4.b32 {%0,%1,%2,%3},[%4];"
                 : "=r"(v.x), "=r"(v.y), "=r"(v.z), "=r"(v.w) : "r"(addr));
    return v;
}
__device__ __forceinline__ void sts128(uint32_t addr, uint4 v) {
    asm volatile("st.shared.v4.b32 [%0],{%1,%2,%3,%4};"
                 :: "r"(addr), "r"(v.x), "r"(v.y), "r"(v.z), "r"(v.w) : "memory");
}
#define GBAR(id) asm volatile("bar.sync %0, 256;" :: "r"(id) : "memory")

__device__ __forceinline__ void mma_f16(float* c, const uint32_t* a, uint32_t b0, uint32_t b1) {
    asm volatile(
        "mma.sync.aligned.m16n8k16.row.col.f32.f16.f16.f32 "
        "{%0,%1,%2,%3},{%4,%5,%6,%7},{%8,%9},{%0,%1,%2,%3};"
        : "+f"(c[0]), "+f"(c[1]), "+f"(c[2]), "+f"(c[3])
        : "r"(a[0]), "r"(a[1]), "r"(a[2]), "r"(a[3]), "r"(b0), "r"(b1));
}

// ---------------- prep kernel (weights only) ----------------
__global__ void prep_w(const float* __restrict__ w) {
    int idx = blockIdx.x * 256 + threadIdx.x;    // 36864 (cblk,kh,kw,oc,slot)
    int slot = idx & 7;
    int oc   = (idx >> 3) & 127;
    int t    = idx >> 10;          // 0..35
    int cblk = t / 9;
    int r9   = t - cblk * 9;
    int kh   = r9 / 3;
    int kw   = r9 - kh * 3;
    int off  = kh * 3 + kw;
    int p    = (slot >> 1) + 4 * (slot & 1);
    int ce   = cblk * 16 + 2 * p;
    uint32_t val = pack_h2(w[oc * 576 + ce * 9 + off], w[oc * 576 + (ce + 1) * 9 + off]);

    int ocb = oc >> 4;
    int ocr = oc & 15;
    int r8  = ocr & 7;
    int hi  = ocr >> 3;
    int n   = (r8 * 4 + (slot >> 1)) * 4 + (slot & 1) * 2 + hi;
    g_a16[t * 1024 + ocb * 128 + n] = val;
}

// ---------------- main kernel ----------------
// 148 persistent CTAs x 512 threads; 2 independent 8-warp groups per CTA.
// All A resident in SMEM; each group streams B for its units.
__global__ __launch_bounds__(512, 1) void conv_main(const float* __restrict__ x,
                                                    float* __restrict__ out) {
    extern __shared__ __align__(16) uint32_t sm[];

    const int tid   = threadIdx.x;
    const int grp   = tid >> 8;
    const int gtid  = tid & 255;
    const int lane  = tid & 31;
    const int gwarp = (tid >> 5) & 7;
    const int wm    = gwarp >> 2;      // 0..1 : oc half
    const int wn    = gwarp & 3;
    const int rW    = wn >> 1;         // output row within pair
    const int cW    = (wn & 1) * 32;   // wo base

    const uint32_t smem_b = cvta_s(sm);

    // ---- copy ALL A tiles into smem (once) ----
    {
        const uint4* as = (const uint4*)g_a16;
        uint4* ad = (uint4*)sm;
        #pragma unroll
        for (int k = 0; k < 18; ++k) {
            int i = tid + k * 512;
            ad[i] = as[i];
        }
    }

    // ---- B staging descriptors (per group thread): 544 x 16B ops ----
    uint32_t boff[3], bdw[3];
    bool bact[3];
    #pragma unroll
    for (int j = 0; j < 3; ++j) {
        int e = gtid + j * 256;
        bact[j] = (e < 544);
        int ee = bact[j] ? e : 0;
        int r  = ee / 17, q = ee - r * 17;
        int qe = (q > 15) ? 15 : q;
        int c2 = r >> 2, row = r & 3;
        boff[j] = (uint32_t)(2 * c2 * 4096 + row * 64 + 4 * qe);     // floats, unit-relative
        bdw[j]  = (uint32_t)(row * (8 * BROWW) + c2 * BROWW + 4 * q); // words, buffer-relative
    }

    // ---- streams ----
    const int stream = blockIdx.x * 2 + grp;
    const int nu = (stream < 104) ? 4 : 3;      // 992 = 296*3 + 104
    const int S  = nu * 4;

    int uid_stage = stream;                      // unit currently being STAGED
    const float* ubase = x + (size_t)(uid_stage & 31) * 262144
                           + (size_t)((uid_stage >> 5) * 2) * 64;
    int uc = stream;                             // unit currently being COMPUTED

    const uint32_t bregw = (uint32_t)(AWORDS + grp * 2 * BBUFW);  // group B region (words)
    const uint32_t a_fw  = (uint32_t)(wm * 512 + lane * 4) * 4;
    const uint32_t b_fwr = (uint32_t)((lane & 3) * BROWW + cW + (lane >> 2)) * 4;

    float acc[4][4][4];
    #pragma unroll
    for (int mi = 0; mi < 4; ++mi)
        #pragma unroll
        for (int ni = 0; ni < 4; ++ni)
            #pragma unroll
            for (int q = 0; q < 4; ++q) acc[mi][ni][q] = 0.0f;

    // ---- prologue: stage B(unit0, s=0) into buf0 ----
    #pragma unroll
    for (int j = 0; j < 3; ++j) {
        if (bact[j]) {
            float4 e = *(const float4*)(ubase + boff[j]);
            float4 o = *(const float4*)(ubase + boff[j] + 4096);
            uint4 v;
            v.x = pack_h2(e.x, o.x); v.y = pack_h2(e.y, o.y);
            v.z = pack_h2(e.z, o.z); v.w = pack_h2(e.w, o.w);
            sts128(smem_b + (bregw + bdw[j]) * 4, v);
        }
    }
    __syncthreads();   // covers A copy + both groups' prologue staging

    #pragma unroll 1
    for (int step = 0; step < S; ++step) {
        const int s   = step & 3;
        const int buf = step & 1;
        const bool hv = (step + 1 < S);

        // staging source for step+1
        uint32_t nso;
        if (s == 3) {
            uid_stage += NSTREAM;
            ubase = x + (size_t)(uid_stage & 31) * 262144
                      + (size_t)((uid_stage >> 5) * 2) * 64;
            nso = 0;
        } else {
            nso = (uint32_t)((s + 1) * 16 * 4096);
        }

        const uint32_t cbw   = bregw + (uint32_t)buf * BBUFW;
        const uint32_t nbw   = bregw + (uint32_t)(buf ^ 1) * BBUFW;
        const uint32_t abase0 = smem_b + (uint32_t)s * 36864 + a_fw;
        const uint32_t bbaseS = smem_b + cbw * 4 + b_fwr;

        #pragma unroll
        for (int ki = 0; ki < 3; ++ki) {
            const int kh = wm ? (2 - ki) : ki;   // stagger

            float4 e, o;
            const bool doB = hv && bact[ki];
            if (doB) {
                e = *(const float4*)(ubase + boff[ki] + nso);
                o = *(const float4*)(ubase + boff[ki] + nso + 4096);
            }

            const uint32_t brow = bbaseS + (uint32_t)((rW + kh) * (8 * BROWW)) * 4;

            #pragma unroll
            for (int kj = 0; kj < 3; ++kj) {
                const int kw = wm ? (2 - kj) : kj;
                const uint32_t abase = abase0 + (uint32_t)(kh * 3 + kw) * 4096;
                const uint32_t bbase = brow + (uint32_t)kw * 4;

                uint32_t bf[4][2];
                #pragma unroll
                for (int ni = 0; ni < 4; ++ni) {
                    bf[ni][0] = lds32(bbase + (uint32_t)ni * 32);
                    bf[ni][1] = lds32(bbase + (uint32_t)ni * 32 + 4 * BROWW * 4);
                }
                #pragma unroll
                for (int mi = 0; mi < 4; ++mi) {
                    uint4 a4 = lds128(abase + (uint32_t)mi * 512);
                    uint32_t af[4] = {a4.x, a4.y, a4.z, a4.w};
                    #pragma unroll
                    for (int ni = 0; ni < 4; ++ni)
                        mma_f16(acc[mi][ni], af, bf[ni][0], bf[ni][1]);
                }
            }

            if (doB) {
                uint4 v;
                v.x = pack_h2(e.x, o.x); v.y = pack_h2(e.y, o.y);
                v.z = pack_h2(e.z, o.z); v.w = pack_h2(e.w, o.w);
                sts128(smem_b + (nbw + bdw[ki]) * 4, v);
            }
        }

        // ---- unit epilogue ----
        if (s == 3) {
            const int b_c  = uc & 31;
            const int orow = (uc >> 5) * 2 + rW;
            #pragma unroll
            for (int mi = 0; mi < 4; ++mi) {
                #pragma unroll
                for (int ni = 0; ni < 4; ++ni) {
                    const int ocr = wm * 64 + mi * 16 + (lane >> 2);
                    const int wo  = cW + ni * 8 + 2 * (lane & 3);
                    if (wo < WO) {
                        const size_t base = (size_t)orow * WO + wo;
                        float* p0 = out + ((size_t)ocr * NB + b_c) * NPB + base;
                        *(float2*)p0 = make_float2(acc[mi][ni][0], acc[mi][ni][1]);
                        float* p1 = out + ((size_t)(ocr + 8) * NB + b_c) * NPB + base;
                        *(float2*)p1 = make_float2(acc[mi][ni][2], acc[mi][ni][3]);
                    }
                }
            }
            #pragma unroll
            for (int mi = 0; mi < 4; ++mi)
                #pragma unroll
                for (int ni = 0; ni < 4; ++ni)
                    #pragma unroll
                    for (int q = 0; q < 4; ++q) acc[mi][ni][q] = 0.0f;
            uc += NSTREAM;
        }

        GBAR(grp + 1);
    }
}

// ---------------- launch ----------------
extern "C" void kernel_launch(void* const* d_in, const int* in_sizes, int n_in,
                              void* d_out, int out_size) {
    const float* x = (const float*)d_in[0];
    const float* w = (const float*)d_in[1];
    float* out = (float*)d_out;

    cudaFuncSetAttribute(conv_main, cudaFuncAttributeMaxDynamicSharedMemorySize, SMEMB);

    prep_w<<<144, 256>>>(w);
    conv_main<<<148, 512, SMEMB>>>(x, out);
}